// round 14
// baseline (speedup 1.0000x reference)
#include <cuda_runtime.h>
#include <cstdint>

#define BB    2048
#define TT    64
#define CC    1024
#define HH    16
#define DKK   8
#define M1M   512
#define M2M   128
#define GRID_ 148
#define SCALE_ 0.35355339059327373f
#define EPS_   1e-5f
#define NEGINF_ (-3.402823466e38f)

// ---------------- device scratch (no allocations allowed) ----------------
__device__ float g_wq[HH * CC];          // folded query projection (scaled)
__device__ float g_pooled[BB * CC];      // attention-pooled features
__device__ int   g_mask_mode;            // 0=u8, 1=i32, 2=f32
__device__ unsigned int g_tk1;           // ticket counter (monotone)
__device__ volatile unsigned int g_rl1;  // release round (monotone)

// ---------------- f32x2 packed-math helpers ----------------
__device__ __forceinline__ void upk2(unsigned long long v, float& lo, float& hi) {
    asm("mov.b64 {%0,%1}, %2;" : "=f"(lo), "=f"(hi) : "l"(v));
}
__device__ __forceinline__ unsigned long long fma2(unsigned long long a,
                                                   unsigned long long b,
                                                   unsigned long long c) {
    unsigned long long d;
    asm("fma.rn.f32x2 %0, %1, %2, %3;" : "=l"(d) : "l"(a), "l"(b), "l"(c));
    return d;
}
__device__ __forceinline__ unsigned long long pk2s(float a) {
    unsigned long long r;
    asm("mov.b64 %0, {%1,%1};" : "=l"(r) : "f"(a));
    return r;
}

// ---------------- replay-safe device-wide barrier (all 148 CTAs resident) ----
__device__ __forceinline__ void gbar(unsigned int* tk, volatile unsigned int* rl) {
    __syncthreads();
    if (threadIdx.x == 0) {
        __threadfence();
        unsigned int t = atomicAdd(tk, 1u) + 1u;
        unsigned int round = (t + GRID_ - 1u) / GRID_;
        if (t == round * GRID_) {
            __threadfence();
            *rl = round;
        } else {
            while (*rl < round) { }
        }
        __threadfence();
    }
    __syncthreads();
}

// ---------------- k_attn smem layout (floats) ----------------
// wq[16384] | xs[2][16384] | att[1024] | p[1024]
#define WQ_OFF   0
#define XS_OFF   16384
#define ATT_OFF  49152
#define PS_OFF   50176
#define SMEM1_F  51200

__device__ __forceinline__ void tile_async512(float* dst, const float* src) {
    int tid = threadIdx.x;
    #pragma unroll
    for (int i = 0; i < 8; i++) {
        int e = (tid + i * 512) * 4;
        uint32_t sa = (uint32_t)__cvta_generic_to_shared(dst + e);
        asm volatile("cp.async.cg.shared.global [%0], [%1], 16;\n"
                     :: "r"(sa), "l"(src + e));
    }
}
#define CP_COMMIT() asm volatile("cp.async.commit_group;\n")
#define CP_WAIT1()  asm volatile("cp.async.wait_group 1;\n")
#define CP_WAIT0()  asm volatile("cp.async.wait_group 0;\n")

// =====================================================================
// K1: 512 threads, 148 CTAs — wq fold + two-pass attention
//   pass A: score GEMM over 4 double-buffered 64KB tiles -> raw scores
//   pass B: exact masked softmax (warp w = head w) -> p_s, attn_out
//   pass C: pool tiles 2,3 from the still-resident buffers, then
//           re-stream tiles 0,1 through the freed buffers via cp.async
//           (L2-hot, latency hidden) and pool from smem.
// =====================================================================
__global__ void __launch_bounds__(512, 1)
k_attn(const float* __restrict__ x, const void* __restrict__ kpm,
       const float* __restrict__ Wk, const float* __restrict__ query,
       float* __restrict__ attn_out) {
    extern __shared__ float smem[];
    const int cta  = blockIdx.x;
    const int tid  = threadIdx.x;
    const int wid  = tid >> 5;
    const int lane = tid & 31;

    // ============ phase 0: CTAs 0..15 build g_wq; CTA0 mask fingerprint ======
    if (cta < 16) {
        float* wk_s = smem + XS_OFF;       // scratch (x staging area)
        float* q_s  = smem + ATT_OFF;
        const int c_base = cta * 64;
        const float4* src = (const float4*)(Wk + c_base * (HH * DKK));
        #pragma unroll
        for (int i = 0; i < 4; i++)
            ((float4*)wk_s)[tid + i * 512] = src[tid + i * 512];
        if (tid < 128) q_s[tid] = query[tid] * SCALE_;
        __syncthreads();
        if (tid < 256) {
            const int h  = tid >> 4;
            const int cl = (tid & 15) * 4;
            #pragma unroll
            for (int j = 0; j < 4; j++) {
                float s = 0.f;
                #pragma unroll
                for (int d = 0; d < DKK; d++)
                    s += q_s[h * DKK + d] * wk_s[(cl + j) * 128 + h * DKK + d];
                g_wq[h * CC + c_base + cl + j] = s;
            }
        }
        if (cta == 0) {
            __shared__ int nonbin, oddpos;
            if (tid == 0) { nonbin = 0; oddpos = 0; }
            __syncthreads();
            if (tid < 256) {
                const unsigned char* p = (const unsigned char*)kpm;
                int lnb = 0, lod = 0;
                int base = tid * 128;
                for (int i = 0; i < 128; i++) {
                    unsigned char v = p[base + i];
                    if (v > 1) lnb = 1;
                    else if (v == 1 && ((base + i) & 3)) lod = 1;
                }
                if (lnb) atomicOr(&nonbin, 1);
                if (lod) atomicOr(&oddpos, 1);
            }
            __syncthreads();
            if (tid == 0) g_mask_mode = nonbin ? 2 : (oddpos ? 0 : 1);
        }
        __syncthreads();
    }
    // everyone prefetches their first batch tile 0 into buf0 before arriving
    tile_async512(smem + XS_OFF, x + (size_t)cta * (TT * CC));
    CP_COMMIT();
    gbar(&g_tk1, &g_rl1);

    // ============ phase 1 =================================================
    float* wq_s  = smem + WQ_OFF;
    float* xs    = smem + XS_OFF;      // 2 x 16384-float tile buffers
    float* att_s = smem + ATT_OFF;     // [16][64] raw scores
    float* p_s   = smem + PS_OFF;      // [16][64] normalized probs

    // stage wq once (coalesced float4)
    #pragma unroll
    for (int i = tid; i < 4096; i += 512)
        ((float4*)wq_s)[i] = ((const float4*)g_wq)[i];

    const int mode = g_mask_mode;
    // 16 warps: rg(4) x hg(4); warp tile = 4 rows x 4 heads x 1024 k
    const int rg = (wid >> 2) * 4;         // tile-local row base
    const int h0 = (wid & 3) * 4;          // head base
    const int hc = tid >> 5;               // pooling head (channels tid*2,+1)

    for (int b = cta; b < BB; b += GRID_) {
        const float* xb = x + (size_t)b * (TT * CC);

        // per-thread mask registers for softmax (t = lane*2, lane*2+1)
        int mk0, mk1;
        {
            const int t0 = lane * 2;
            if (mode == 0) {
                const unsigned char* p = (const unsigned char*)kpm + b * TT;
                mk0 = p[t0] != 0; mk1 = p[t0 + 1] != 0;
            } else if (mode == 1) {
                const int* p = (const int*)kpm + b * TT;
                mk0 = p[t0] != 0; mk1 = p[t0 + 1] != 0;
            } else {
                const float* p = (const float*)kpm + b * TT;
                mk0 = p[t0] != 0.f; mk1 = p[t0 + 1] != 0.f;
            }
        }

        // ---- pass A: score GEMM, 4 tiles (after loop: buf0=tile2, buf1=tile3)
        for (int tile = 0; tile < 4; tile++) {
            CP_WAIT0();
            __syncthreads();   // tile data arrived AND previous readers done
            if (tile < 3) {
                tile_async512(xs + ((tile + 1) & 1) * 16384, xb + (tile + 1) * 16384);
                CP_COMMIT();
            }

            float* xt = xs + (tile & 1) * 16384;
            const ulonglong2* xb2 = (const ulonglong2*)xt + rg * 256;   // 256 ull2/row
            const ulonglong2* wb2 = (const ulonglong2*)wq_s + h0 * 256;

            unsigned long long acc[4][4];
            #pragma unroll
            for (int r = 0; r < 4; r++)
                #pragma unroll
                for (int h = 0; h < 4; h++) acc[r][h] = 0ull;

            #pragma unroll
            for (int it = 0; it < 8; it++) {
                const int ci = lane + it * 32;
                ulonglong2 X0 = xb2[0 * 256 + ci];
                ulonglong2 X1 = xb2[1 * 256 + ci];
                ulonglong2 X2 = xb2[2 * 256 + ci];
                ulonglong2 X3 = xb2[3 * 256 + ci];
                #pragma unroll
                for (int h = 0; h < 4; h++) {
                    ulonglong2 W = wb2[h * 256 + ci];
                    acc[0][h] = fma2(X0.x, W.x, acc[0][h]); acc[0][h] = fma2(X0.y, W.y, acc[0][h]);
                    acc[1][h] = fma2(X1.x, W.x, acc[1][h]); acc[1][h] = fma2(X1.y, W.y, acc[1][h]);
                    acc[2][h] = fma2(X2.x, W.x, acc[2][h]); acc[2][h] = fma2(X2.y, W.y, acc[2][h]);
                    acc[3][h] = fma2(X3.x, W.x, acc[3][h]); acc[3][h] = fma2(X3.y, W.y, acc[3][h]);
                }
            }

            // staggered per-row reduction; write raw scores
            #pragma unroll
            for (int r = 0; r < 4; r++) {
                float sv[4];
                #pragma unroll
                for (int h = 0; h < 4; h++) {
                    float lo, hi; upk2(acc[r][h], lo, hi);
                    sv[h] = lo + hi;
                }
                #pragma unroll
                for (int off = 16; off; off >>= 1)
                    #pragma unroll
                    for (int h = 0; h < 4; h++)
                        sv[h] += __shfl_xor_sync(0xffffffffu, sv[h], off);
                float v = sv[0];
                #pragma unroll
                for (int h = 1; h < 4; h++) v = (lane == h) ? sv[h] : v;
                if (lane < 4)
                    att_s[(h0 + lane) * TT + tile * 16 + rg + r] = v;
            }
        }
        __syncthreads();   // all scores written

        // ---- pass B: exact masked softmax, warp w = head w ----
        {
            const int h  = wid;
            const int t0 = lane * 2;
            float2 sv = *(const float2*)(att_s + h * TT + t0);
            float a0 = mk0 ? NEGINF_ : sv.x;
            float a1 = mk1 ? NEGINF_ : sv.y;
            float mx = fmaxf(a0, a1);
            #pragma unroll
            for (int off = 16; off; off >>= 1)
                mx = fmaxf(mx, __shfl_xor_sync(0xffffffffu, mx, off));
            float e0 = mk0 ? 0.f : __expf(sv.x - mx);
            float e1 = mk1 ? 0.f : __expf(sv.y - mx);
            float sm = e0 + e1;
            #pragma unroll
            for (int off = 16; off; off >>= 1)
                sm += __shfl_xor_sync(0xffffffffu, sm, off);
            float inv = 1.f / sm;
            float2 o; o.x = e0 * inv; o.y = e1 * inv;
            *(float2*)(p_s + h * TT + t0) = o;
            *(float2*)(attn_out + (size_t)b * (HH * TT) + h * TT + t0) = o;
        }
        __syncthreads();   // p_s ready (also: all pass-A buffer reads done)

        // ---- pass C: smem pooling ----
        unsigned long long pac = 0ull;
        const float* pp = p_s + hc * TT;
        // tiles 2,3 are still resident (buf0=tile2, buf1=tile3)
        #pragma unroll
        for (int half = 0; half < 2; half++) {
            const float* xt = xs + half * 16384 + tid * 2;
            const float* ppt = pp + (2 + half) * 16;
            #pragma unroll
            for (int tt = 0; tt < 16; tt++) {
                float p = ppt[tt];
                float2 v = *(const float2*)(xt + tt * CC);
                pac = fma2(pk2s(p), *(unsigned long long*)&v, pac);
            }
        }
        __syncthreads();   // tiles 2,3 fully pooled -> buffers free
        // re-stream tiles 0,1 (L2-hot) into the freed buffers
        tile_async512(xs, xb);
        CP_COMMIT();
        tile_async512(xs + 16384, xb + 16384);
        CP_COMMIT();
        CP_WAIT1();        // own tile-0 copies done
        __syncthreads();   // tile 0 visible to all
        {
            const float* xt = xs + tid * 2;
            const float* ppt = pp;
            #pragma unroll
            for (int tt = 0; tt < 16; tt++) {
                float p = ppt[tt];
                float2 v = *(const float2*)(xt + tt * CC);
                pac = fma2(pk2s(p), *(unsigned long long*)&v, pac);
            }
        }
        CP_WAIT0();        // own tile-1 copies done
        __syncthreads();   // tile 1 visible; buf0 pooling reads done
        {
            const float* xt = xs + 16384 + tid * 2;
            const float* ppt = pp + 16;
            #pragma unroll
            for (int tt = 0; tt < 16; tt++) {
                float p = ppt[tt];
                float2 v = *(const float2*)(xt + tt * CC);
                pac = fma2(pk2s(p), *(unsigned long long*)&v, pac);
            }
        }
        {
            float px, py; upk2(pac, px, py);
            *(float2*)(g_pooled + (size_t)b * CC + tid * 2) = make_float2(px, py);
        }
        // prefetch next batch tile 0 into buf0 (buf0 reads finished before the
        // last __syncthreads; buf1 reads are ordered by next batch's first
        // CP_WAIT0+__syncthreads before buf1 is written at tile 0's prefetch)
        if (b + GRID_ < BB) {
            tile_async512(xs, x + (size_t)(b + GRID_) * (TT * CC));
            CP_COMMIT();
        }
    }
}

// ---------------- no-op kernel: shifts ncu's -s 5 onto k_attn ------------
__global__ void k_noop() {}

// =====================================================================
// K2: MLP — proven cp.async + splat kernel (R11, 96 us). Unchanged.
// =====================================================================
#define P2_A     0
#define P2_WB    16384
#define P2_SP    32768
#define P2_YS    36864
#define P2_Y2    45056
#define P2_ST    47104
#define SMEM2_F  47168

__device__ __forceinline__ void wtile_async(float* dst, const float* src) {
    int tid = threadIdx.x;
    #pragma unroll
    for (int i = 0; i < 8; i++) {
        int e = (tid + i * 256) * 4;
        uint32_t sa = (uint32_t)__cvta_generic_to_shared(dst + e);
        asm volatile("cp.async.cg.shared.global [%0], [%1], 16;\n"
                     :: "r"(sa), "l"(src + e));
    }
}

__global__ void __launch_bounds__(256, 1)
k_mlp(const float* __restrict__ W1, const float* __restrict__ g1,
      const float* __restrict__ b1, const float* __restrict__ W2,
      const float* __restrict__ g2, const float* __restrict__ b2,
      float* __restrict__ out) {
    extern __shared__ float smem[];
    float* A   = smem + P2_A;
    float* ys  = smem + P2_YS;
    float* y2s = smem + P2_Y2;
    float* mu1 = smem + P2_ST;
    float* rs1 = mu1 + 16;
    float* mu2 = rs1 + 16;
    float* rs2 = mu2 + 16;

    const int cta  = blockIdx.x;
    const int tid  = threadIdx.x;
    const int wid  = tid >> 5;
    const int lane = tid & 31;
    const int b0   = cta * 16;

    for (int i = tid; i < 4096; i += 256)
        ((float4*)A)[i] = *(const float4*)(g_pooled + (size_t)b0 * CC + i * 4);

    wtile_async(smem + P2_WB, W1);
    CP_COMMIT();
    wtile_async(smem + P2_WB + 8192, W1 + 8192);
    CP_COMMIT();
    __syncthreads();

    // ---- GEMM1: 16x512x1024, thread = 4 cols x 8 rows ----
    const int cg  = tid & 127;
    const int rg2 = tid >> 7;
    unsigned long long acc[8][2];
    #pragma unroll
    for (int r = 0; r < 8; r++) { acc[r][0] = 0ull; acc[r][1] = 0ull; }

    const int kk_b = tid >> 4, r_b = tid & 15;
    for (int kt = 0; kt < 64; kt++) {
        float* wb = smem + P2_WB + (kt & 1) * 8192;
        float* sp = smem + P2_SP + (kt & 1) * 2048;
        if (kt < 63) CP_WAIT1(); else CP_WAIT0();
        {
            float a = A[r_b * CC + kt * 16 + kk_b];
            ((float2*)sp)[kk_b * 16 + r_b] = make_float2(a, a);
        }
        __syncthreads();
        #pragma unroll
        for (int kk = 0; kk < 16; kk++) {
            ulonglong2 w = *(const ulonglong2*)(wb + kk * 512 + cg * 4);
            const float* aspk = sp + (kk * 16 + rg2 * 8) * 2;
            #pragma unroll
            for (int j = 0; j < 4; j++) {
                ulonglong2 a2 = *(const ulonglong2*)(aspk + j * 4);
                acc[2*j  ][0] = fma2(a2.x, w.x, acc[2*j  ][0]);
                acc[2*j  ][1] = fma2(a2.x, w.y, acc[2*j  ][1]);
                acc[2*j+1][0] = fma2(a2.y, w.x, acc[2*j+1][0]);
                acc[2*j+1][1] = fma2(a2.y, w.y, acc[2*j+1][1]);
            }
        }
        __syncthreads();
        if (kt + 2 < 64) {
            wtile_async(smem + P2_WB + (kt & 1) * 8192, W1 + (kt + 2) * 8192);
            CP_COMMIT();
        }
    }
    #pragma unroll
    for (int r = 0; r < 8; r++) {
        float c0, c1, c2, c3;
        upk2(acc[r][0], c0, c1);
        upk2(acc[r][1], c2, c3);
        *(float4*)(ys + (rg2 * 8 + r) * M1M + cg * 4) = make_float4(c0, c1, c2, c3);
    }
    __syncthreads();

    // ---- LN1 ----
    for (int r = wid; r < 16; r += 8) {
        float s = 0.f, ss = 0.f;
        #pragma unroll
        for (int j = 0; j < 16; j++) {
            float v = ys[r * M1M + lane + j * 32];
            s += v; ss += v * v;
        }
        #pragma unroll
        for (int off = 16; off; off >>= 1) {
            s  += __shfl_xor_sync(0xffffffffu, s, off);
            ss += __shfl_xor_sync(0xffffffffu, ss, off);
        }
        if (lane == 0) {
            float mu = s * (1.f / M1M);
            float var = ss * (1.f / M1M) - mu * mu;
            mu1[r] = mu;
            rs1[r] = rsqrtf(var + EPS_);
        }
    }
    __syncthreads();
    {
        float2 gv = ((const float2*)g1)[tid];
        float2 bv = ((const float2*)b1)[tid];
        #pragma unroll
        for (int r = 0; r < 16; r++) {
            float m = mu1[r], rs = rs1[r];
            float2 v = *(float2*)(ys + r * M1M + 2 * tid);
            v.x = fmaxf(0.f, (v.x - m) * rs * gv.x + bv.x);
            v.y = fmaxf(0.f, (v.y - m) * rs * gv.y + bv.y);
            *(float2*)(ys + r * M1M + 2 * tid) = v;
        }
    }
    __syncthreads();

    // ---- GEMM2: 16x128x512 ----
    wtile_async(smem + P2_WB, W2);
    CP_COMMIT();
    wtile_async(smem + P2_WB + 8192, W2 + 8192);
    CP_COMMIT();

    const int cp2 = tid & 63;
    const int rg4 = tid >> 6;
    unsigned long long acc2[4] = {0ull, 0ull, 0ull, 0ull};

    for (int kt = 0; kt < 8; kt++) {
        float* wb = smem + P2_WB + (kt & 1) * 8192;
        float* sp = smem + P2_SP + (kt & 1) * 2048;
        if (kt < 7) CP_WAIT1(); else CP_WAIT0();
        for (int i = tid; i < 1024; i += 256) {
            int kk = i >> 4, r = i & 15;
            float v = ys[r * M1M + kt * 64 + kk];
            ((float2*)sp)[i] = make_float2(v, v);
        }
        __syncthreads();
        #pragma unroll
        for (int kk = 0; kk < 64; kk++) {
            unsigned long long w = *(const unsigned long long*)(wb + kk * 128 + cp2 * 2);
            const float* hk = sp + (kk * 16 + rg4 * 4) * 2;
            ulonglong2 h01 = *(const ulonglong2*)(hk);
            ulonglong2 h23 = *(const ulonglong2*)(hk + 4);
            acc2[0] = fma2(h01.x, w, acc2[0]);
            acc2[1] = fma2(h01.y, w, acc2[1]);
            acc2[2] = fma2(h23.x, w, acc2[2]);
            acc2[3] = fma2(h23.y, w, acc2[3]);
        }
        __syncthreads();
        if (kt + 2 < 8) {
            wtile_async(smem + P2_WB + (kt & 1) * 8192, W2 + (kt + 2) * 8192);
            CP_COMMIT();
        }
    }
    #pragma unroll
    for (int j = 0; j < 4; j++) {
        float c0, c1;
        upk2(acc2[j], c0, c1);
        *(float2*)(y2s + (rg4 * 4 + j) * M2M + cp2 * 2) = make_float2(c0, c1);
    }
    __syncthreads();

    // ---- LN2 + output ----
    for (int r = wid; r < 16; r += 8) {
        float s = 0.f, ss = 0.f;
        #pragma unroll
        for (int j = 0; j < 4; j++) {
            float v = y2s[r * M2M + lane + j * 32];
            s += v; ss += v * v;
        }
        #pragma unroll
        for (int off = 16; off; off >>= 1) {
            s  += __shfl_xor_sync(0xffffffffu, s, off);
            ss += __shfl_xor_sync(0xffffffffu, ss, off);
        }
        if (lane == 0) {
            float mu = s * (1.f / M2M);
            float var = ss * (1.f / M2M) - mu * mu;
            mu2[r] = mu;
            rs2[r] = rsqrtf(var + EPS_);
        }
    }
    __syncthreads();
    {
        const int m  = tid & 127;
        const int rb = (tid >> 7) * 8;
        float gv = g2[m], bv = b2[m];
        #pragma unroll
        for (int j = 0; j < 8; j++) {
            int r = rb + j;
            float v = (y2s[r * M2M + m] - mu2[r]) * rs2[r] * gv + bv;
            out[(size_t)(b0 + r) * M2M + m] = fmaxf(0.f, v);
        }
    }
}

// ---------------- launcher ----------------
extern "C" void kernel_launch(void* const* d_in, const int* in_sizes, int n_in,
                              void* d_out, int out_size) {
    const float* x     = (const float*)d_in[0];
    const void*  kpm   = d_in[2];
    const float* Wk    = (const float*)d_in[3];
    const float* query = (const float*)d_in[5];
    const float* W1    = (const float*)d_in[6];
    const float* g1    = (const float*)d_in[7];
    const float* b1    = (const float*)d_in[8];
    const float* W2    = (const float*)d_in[9];
    const float* g2    = (const float*)d_in[10];
    const float* b2    = (const float*)d_in[11];

    float* out_mlp  = (float*)d_out;                       // [B, 128]
    float* out_attn = (float*)d_out + (size_t)BB * M2M;    // [B, H, T]

    cudaFuncSetAttribute(k_attn, cudaFuncAttributeMaxDynamicSharedMemorySize,
                         SMEM1_F * 4);
    cudaFuncSetAttribute(k_mlp, cudaFuncAttributeMaxDynamicSharedMemorySize,
                         SMEM2_F * 4);

    k_attn<<<GRID_, 512, SMEM1_F * 4>>>(x, kpm, Wk, query, out_attn);
    k_mlp<<<BB / 16, 256, SMEM2_F * 4>>>(W1, g1, b1, W2, g2, b2, out_mlp);
    // 3 no-op launches: 5 launches/call puts ncu's "-s 5" capture (launch #6)
    // on k_attn (position 1 of the second replay) instead of k_mlp.
    k_noop<<<1, 32>>>();
    k_noop<<<1, 32>>>();
    k_noop<<<1, 32>>>();
}

// round 15
// speedup vs baseline: 1.0435x; 1.0435x over previous
#include <cuda_runtime.h>
#include <cstdint>

#define BB    2048
#define TT    64
#define CC    1024
#define HH    16
#define DKK   8
#define M1M   512
#define M2M   128
#define GRID_ 148
#define SCALE_ 0.35355339059327373f
#define EPS_   1e-5f
#define NEGINF_ (-3.402823466e38f)

// ---------------- device scratch (no allocations allowed) ----------------
__device__ float g_wq[HH * CC];          // folded query projection (scaled)
__device__ float g_pooled[BB * CC];      // attention-pooled features
__device__ int   g_mask_mode;            // 0=u8, 1=i32, 2=f32
__device__ unsigned int g_tk1;           // ticket counter (monotone)
__device__ volatile unsigned int g_rl1;  // release round (monotone)

// ---------------- f32x2 packed-math helpers ----------------
__device__ __forceinline__ void upk2(unsigned long long v, float& lo, float& hi) {
    asm("mov.b64 {%0,%1}, %2;" : "=f"(lo), "=f"(hi) : "l"(v));
}
__device__ __forceinline__ unsigned long long fma2(unsigned long long a,
                                                   unsigned long long b,
                                                   unsigned long long c) {
    unsigned long long d;
    asm("fma.rn.f32x2 %0, %1, %2, %3;" : "=l"(d) : "l"(a), "l"(b), "l"(c));
    return d;
}
__device__ __forceinline__ unsigned long long pk2s(float a) {
    unsigned long long r;
    asm("mov.b64 %0, {%1,%1};" : "=l"(r) : "f"(a));
    return r;
}

// ---------------- replay-safe device-wide barrier (all 148 CTAs resident) ----
__device__ __forceinline__ void gbar(unsigned int* tk, volatile unsigned int* rl) {
    __syncthreads();
    if (threadIdx.x == 0) {
        __threadfence();
        unsigned int t = atomicAdd(tk, 1u) + 1u;
        unsigned int round = (t + GRID_ - 1u) / GRID_;
        if (t == round * GRID_) {
            __threadfence();
            *rl = round;
        } else {
            while (*rl < round) { }
        }
        __threadfence();
    }
    __syncthreads();
}

// ---------------- k_attn smem layout (floats) ----------------
#define WQ_OFF   0
#define XS_OFF   16384
#define ATT_OFF  49152
#define P_OFF    50176
#define MR_OFF   50432
#define SR_OFF   50448
#define FS_OFF   50464
#define MSK_OFF  50480
#define SMEM1_F  50544

__device__ __forceinline__ void tile_async512(float* dst, const float* src) {
    int tid = threadIdx.x;
    #pragma unroll
    for (int i = 0; i < 8; i++) {
        int e = (tid + i * 512) * 4;
        uint32_t sa = (uint32_t)__cvta_generic_to_shared(dst + e);
        asm volatile("cp.async.cg.shared.global [%0], [%1], 16;\n"
                     :: "r"(sa), "l"(src + e));
    }
}
#define CP_COMMIT() asm volatile("cp.async.commit_group;\n")
#define CP_WAIT1()  asm volatile("cp.async.wait_group 1;\n")
#define CP_WAIT0()  asm volatile("cp.async.wait_group 0;\n")

// ---------------- no-op kernel: occupies launches 1-3 so ncu's capture
// (empirically the 4th launch of the process) lands on k_attn -------------
__global__ void k_noop() {}

// =====================================================================
// K1: 512 threads, 148 CTAs — wq fold + flash attention (R11 body,
// best standalone attention variant: 4r x 4h x 1024k warp tile)
// =====================================================================
__global__ void __launch_bounds__(512, 1)
k_attn(const float* __restrict__ x, const void* __restrict__ kpm,
       const float* __restrict__ Wk, const float* __restrict__ query,
       float* __restrict__ attn_out) {
    extern __shared__ float smem[];
    const int cta  = blockIdx.x;
    const int tid  = threadIdx.x;
    const int wid  = tid >> 5;
    const int lane = tid & 31;

    // ============ phase 0: CTAs 0..15 build g_wq; CTA0 mask fingerprint ======
    if (cta < 16) {
        float* wk_s = smem + XS_OFF;       // scratch
        float* q_s  = smem + ATT_OFF;
        const int c_base = cta * 64;
        const float4* src = (const float4*)(Wk + c_base * (HH * DKK));
        #pragma unroll
        for (int i = 0; i < 4; i++)
            ((float4*)wk_s)[tid + i * 512] = src[tid + i * 512];
        if (tid < 128) q_s[tid] = query[tid] * SCALE_;
        __syncthreads();
        if (tid < 256) {
            const int h  = tid >> 4;
            const int cl = (tid & 15) * 4;
            #pragma unroll
            for (int j = 0; j < 4; j++) {
                float s = 0.f;
                #pragma unroll
                for (int d = 0; d < DKK; d++)
                    s += q_s[h * DKK + d] * wk_s[(cl + j) * 128 + h * DKK + d];
                g_wq[h * CC + c_base + cl + j] = s;
            }
        }
        if (cta == 0) {
            __shared__ int nonbin, oddpos;
            if (tid == 0) { nonbin = 0; oddpos = 0; }
            __syncthreads();
            if (tid < 256) {
                const unsigned char* p = (const unsigned char*)kpm;
                int lnb = 0, lod = 0;
                int base = tid * 128;
                for (int i = 0; i < 128; i++) {
                    unsigned char v = p[base + i];
                    if (v > 1) lnb = 1;
                    else if (v == 1 && ((base + i) & 3)) lod = 1;
                }
                if (lnb) atomicOr(&nonbin, 1);
                if (lod) atomicOr(&oddpos, 1);
            }
            __syncthreads();
            if (tid == 0) g_mask_mode = nonbin ? 2 : (oddpos ? 0 : 1);
        }
        __syncthreads();
    }
    // everyone prefetches their first batch tile 0 before arriving
    tile_async512(smem + XS_OFF, x + (size_t)cta * (TT * CC));
    CP_COMMIT();
    gbar(&g_tk1, &g_rl1);

    // ============ phase 1 =================================================
    float* wq_s  = smem + WQ_OFF;
    float* xs    = smem + XS_OFF;
    float* att_s = smem + ATT_OFF;
    float* p_s   = smem + P_OFF;
    float* mrun  = smem + MR_OFF;
    float* srun  = smem + SR_OFF;
    float* fsc   = smem + FS_OFF;
    int*   msk_s = (int*)(smem + MSK_OFF);

    // stage wq once (coalesced float4)
    #pragma unroll
    for (int i = tid; i < 4096; i += 512)
        ((float4*)wq_s)[i] = ((const float4*)g_wq)[i];

    const int mode = g_mask_mode;
    // 16 warps: rg(4) x hg(4); warp tile = 4 rows x 4 heads x 1024 k
    const int rg = (wid >> 2) * 4;         // tile-local row base
    const int h0 = (wid & 3) * 4;          // head base
    const int hc = tid >> 5;               // pooling head (channels tid*2,+1)

    for (int b = cta; b < BB; b += GRID_) {
        const float* xb = x + (size_t)b * (TT * CC);
        __syncthreads();                     // protect smem state reuse
        if (tid < TT) {
            int mv;
            if (mode == 0)      mv = ((const unsigned char*)kpm)[b * TT + tid] != 0;
            else if (mode == 1) mv = ((const int*)kpm)[b * TT + tid] != 0;
            else                mv = ((const float*)kpm)[b * TT + tid] != 0.f;
            msk_s[tid] = mv;
        }
        if (tid < HH) { mrun[tid] = NEGINF_; srun[tid] = 0.f; }

        float pacx = 0.f, pacy = 0.f;

        for (int tile = 0; tile < 4; tile++) {
            int issued = 0;
            if (tile < 3) {
                tile_async512(xs + ((tile + 1) & 1) * 16384, xb + (tile + 1) * 16384);
                CP_COMMIT(); issued = 1;
            } else if (b + GRID_ < BB) {
                tile_async512(xs, x + (size_t)(b + GRID_) * (TT * CC));
                CP_COMMIT(); issued = 1;
            }
            if (issued) CP_WAIT1(); else CP_WAIT0();
            __syncthreads();

            float* xt = xs + (tile & 1) * 16384;
            const ulonglong2* xb2 = (const ulonglong2*)xt + rg * 256;   // 256 ull2/row
            const ulonglong2* wb2 = (const ulonglong2*)wq_s + h0 * 256;

            unsigned long long acc[4][4];
            #pragma unroll
            for (int r = 0; r < 4; r++)
                #pragma unroll
                for (int h = 0; h < 4; h++) acc[r][h] = 0ull;

            #pragma unroll
            for (int it = 0; it < 8; it++) {
                const int ci = lane + it * 32;
                ulonglong2 X0 = xb2[0 * 256 + ci];
                ulonglong2 X1 = xb2[1 * 256 + ci];
                ulonglong2 X2 = xb2[2 * 256 + ci];
                ulonglong2 X3 = xb2[3 * 256 + ci];
                #pragma unroll
                for (int h = 0; h < 4; h++) {
                    ulonglong2 W = wb2[h * 256 + ci];
                    acc[0][h] = fma2(X0.x, W.x, acc[0][h]); acc[0][h] = fma2(X0.y, W.y, acc[0][h]);
                    acc[1][h] = fma2(X1.x, W.x, acc[1][h]); acc[1][h] = fma2(X1.y, W.y, acc[1][h]);
                    acc[2][h] = fma2(X2.x, W.x, acc[2][h]); acc[2][h] = fma2(X2.y, W.y, acc[2][h]);
                    acc[3][h] = fma2(X3.x, W.x, acc[3][h]); acc[3][h] = fma2(X3.y, W.y, acc[3][h]);
                }
            }

            // staggered per-row reduction; direct write (no k-split)
            #pragma unroll
            for (int r = 0; r < 4; r++) {
                float sv[4];
                #pragma unroll
                for (int h = 0; h < 4; h++) {
                    float lo, hi; upk2(acc[r][h], lo, hi);
                    sv[h] = lo + hi;
                }
                #pragma unroll
                for (int off = 16; off; off >>= 1)
                    #pragma unroll
                    for (int h = 0; h < 4; h++)
                        sv[h] += __shfl_xor_sync(0xffffffffu, sv[h], off);
                float v = sv[0];
                #pragma unroll
                for (int h = 1; h < 4; h++) v = (lane == h) ? sv[h] : v;
                if (lane < 4)
                    att_s[(h0 + lane) * TT + tile * 16 + rg + r] = v;
            }
            __syncthreads();

            // flash update: warps 0..7 handle heads 2w, 2w+1 (16 lanes each)
            if (wid < 8) {
                const int h  = wid * 2 + (lane >> 4);
                const int tt = lane & 15;
                const int tg = tile * 16 + tt;
                float s_raw  = att_s[h * TT + tg];
                int   msk    = msk_s[tg];
                float sm     = msk ? NEGINF_ : s_raw;
                float tmax   = sm;
                #pragma unroll
                for (int off = 8; off; off >>= 1)
                    tmax = fmaxf(tmax, __shfl_xor_sync(0xffffffffu, tmax, off));
                float m_old = mrun[h];
                float m_new = fmaxf(m_old, tmax);
                float p     = msk ? 0.f : __expf(s_raw - m_new);
                float psum  = p;
                #pragma unroll
                for (int off = 8; off; off >>= 1)
                    psum += __shfl_xor_sync(0xffffffffu, psum, off);
                float f = __expf(m_old - m_new);
                p_s[h * 16 + tt] = p;
                if ((lane & 15) == 0) {
                    mrun[h] = m_new;
                    srun[h] = srun[h] * f + psum;
                    fsc[h]  = f;
                }
            }
            __syncthreads();

            { // pooled accumulation from resident smem tile: 2 channels/thread
                float f = fsc[hc];
                pacx *= f; pacy *= f;
                const float* xp = xt + tid * 2;
                const float* pp = p_s + hc * 16;
                #pragma unroll
                for (int t = 0; t < 16; t++) {
                    float p = pp[t];
                    float2 v = *(const float2*)(xp + t * CC);
                    pacx += p * v.x; pacy += p * v.y;
                }
            }
            __syncthreads();
        }

        { // finalize: attn output + pooled
            const int h  = tid >> 5;          // == hc
            const int tp = lane * 2;
            float m   = mrun[h];
            float inv = 1.f / srun[h];
            float2 o;
            o.x = msk_s[tp]     ? 0.f : __expf(att_s[h * TT + tp]     - m) * inv;
            o.y = msk_s[tp + 1] ? 0.f : __expf(att_s[h * TT + tp + 1] - m) * inv;
            *(float2*)(attn_out + (size_t)b * (HH * TT) + h * TT + tp) = o;

            float invp = 1.f / srun[hc];
            float2 pv; pv.x = pacx * invp; pv.y = pacy * invp;
            *(float2*)(g_pooled + (size_t)b * CC + tid * 2) = pv;
        }
    }
}

// =====================================================================
// K2: MLP — proven cp.async + splat kernel (R11, 96 us). Unchanged.
// =====================================================================
#define P2_A     0
#define P2_WB    16384
#define P2_SP    32768
#define P2_YS    36864
#define P2_Y2    45056
#define P2_ST    47104
#define SMEM2_F  47168

__device__ __forceinline__ void wtile_async(float* dst, const float* src) {
    int tid = threadIdx.x;
    #pragma unroll
    for (int i = 0; i < 8; i++) {
        int e = (tid + i * 256) * 4;
        uint32_t sa = (uint32_t)__cvta_generic_to_shared(dst + e);
        asm volatile("cp.async.cg.shared.global [%0], [%1], 16;\n"
                     :: "r"(sa), "l"(src + e));
    }
}

__global__ void __launch_bounds__(256, 1)
k_mlp(const float* __restrict__ W1, const float* __restrict__ g1,
      const float* __restrict__ b1, const float* __restrict__ W2,
      const float* __restrict__ g2, const float* __restrict__ b2,
      float* __restrict__ out) {
    extern __shared__ float smem[];
    float* A   = smem + P2_A;
    float* ys  = smem + P2_YS;
    float* y2s = smem + P2_Y2;
    float* mu1 = smem + P2_ST;
    float* rs1 = mu1 + 16;
    float* mu2 = rs1 + 16;
    float* rs2 = mu2 + 16;

    const int cta  = blockIdx.x;
    const int tid  = threadIdx.x;
    const int wid  = tid >> 5;
    const int lane = tid & 31;
    const int b0   = cta * 16;

    for (int i = tid; i < 4096; i += 256)
        ((float4*)A)[i] = *(const float4*)(g_pooled + (size_t)b0 * CC + i * 4);

    wtile_async(smem + P2_WB, W1);
    CP_COMMIT();
    wtile_async(smem + P2_WB + 8192, W1 + 8192);
    CP_COMMIT();
    __syncthreads();

    // ---- GEMM1: 16x512x1024, thread = 4 cols x 8 rows ----
    const int cg  = tid & 127;
    const int rg2 = tid >> 7;
    unsigned long long acc[8][2];
    #pragma unroll
    for (int r = 0; r < 8; r++) { acc[r][0] = 0ull; acc[r][1] = 0ull; }

    const int kk_b = tid >> 4, r_b = tid & 15;
    for (int kt = 0; kt < 64; kt++) {
        float* wb = smem + P2_WB + (kt & 1) * 8192;
        float* sp = smem + P2_SP + (kt & 1) * 2048;
        if (kt < 63) CP_WAIT1(); else CP_WAIT0();
        {
            float a = A[r_b * CC + kt * 16 + kk_b];
            ((float2*)sp)[kk_b * 16 + r_b] = make_float2(a, a);
        }
        __syncthreads();
        #pragma unroll
        for (int kk = 0; kk < 16; kk++) {
            ulonglong2 w = *(const ulonglong2*)(wb + kk * 512 + cg * 4);
            const float* aspk = sp + (kk * 16 + rg2 * 8) * 2;
            #pragma unroll
            for (int j = 0; j < 4; j++) {
                ulonglong2 a2 = *(const ulonglong2*)(aspk + j * 4);
                acc[2*j  ][0] = fma2(a2.x, w.x, acc[2*j  ][0]);
                acc[2*j  ][1] = fma2(a2.x, w.y, acc[2*j  ][1]);
                acc[2*j+1][0] = fma2(a2.y, w.x, acc[2*j+1][0]);
                acc[2*j+1][1] = fma2(a2.y, w.y, acc[2*j+1][1]);
            }
        }
        __syncthreads();
        if (kt + 2 < 64) {
            wtile_async(smem + P2_WB + (kt & 1) * 8192, W1 + (kt + 2) * 8192);
            CP_COMMIT();
        }
    }
    #pragma unroll
    for (int r = 0; r < 8; r++) {
        float c0, c1, c2, c3;
        upk2(acc[r][0], c0, c1);
        upk2(acc[r][1], c2, c3);
        *(float4*)(ys + (rg2 * 8 + r) * M1M + cg * 4) = make_float4(c0, c1, c2, c3);
    }
    __syncthreads();

    // ---- LN1 ----
    for (int r = wid; r < 16; r += 8) {
        float s = 0.f, ss = 0.f;
        #pragma unroll
        for (int j = 0; j < 16; j++) {
            float v = ys[r * M1M + lane + j * 32];
            s += v; ss += v * v;
        }
        #pragma unroll
        for (int off = 16; off; off >>= 1) {
            s  += __shfl_xor_sync(0xffffffffu, s, off);
            ss += __shfl_xor_sync(0xffffffffu, ss, off);
        }
        if (lane == 0) {
            float mu = s * (1.f / M1M);
            float var = ss * (1.f / M1M) - mu * mu;
            mu1[r] = mu;
            rs1[r] = rsqrtf(var + EPS_);
        }
    }
    __syncthreads();
    {
        float2 gv = ((const float2*)g1)[tid];
        float2 bv = ((const float2*)b1)[tid];
        #pragma unroll
        for (int r = 0; r < 16; r++) {
            float m = mu1[r], rs = rs1[r];
            float2 v = *(float2*)(ys + r * M1M + 2 * tid);
            v.x = fmaxf(0.f, (v.x - m) * rs * gv.x + bv.x);
            v.y = fmaxf(0.f, (v.y - m) * rs * gv.y + bv.y);
            *(float2*)(ys + r * M1M + 2 * tid) = v;
        }
    }
    __syncthreads();

    // ---- GEMM2: 16x128x512 ----
    wtile_async(smem + P2_WB, W2);
    CP_COMMIT();
    wtile_async(smem + P2_WB + 8192, W2 + 8192);
    CP_COMMIT();

    const int cp2 = tid & 63;
    const int rg4 = tid >> 6;
    unsigned long long acc2[4] = {0ull, 0ull, 0ull, 0ull};

    for (int kt = 0; kt < 8; kt++) {
        float* wb = smem + P2_WB + (kt & 1) * 8192;
        float* sp = smem + P2_SP + (kt & 1) * 2048;
        if (kt < 7) CP_WAIT1(); else CP_WAIT0();
        for (int i = tid; i < 1024; i += 256) {
            int kk = i >> 4, r = i & 15;
            float v = ys[r * M1M + kt * 64 + kk];
            ((float2*)sp)[i] = make_float2(v, v);
        }
        __syncthreads();
        #pragma unroll
        for (int kk = 0; kk < 64; kk++) {
            unsigned long long w = *(const unsigned long long*)(wb + kk * 128 + cp2 * 2);
            const float* hk = sp + (kk * 16 + rg4 * 4) * 2;
            ulonglong2 h01 = *(const ulonglong2*)(hk);
            ulonglong2 h23 = *(const ulonglong2*)(hk + 4);
            acc2[0] = fma2(h01.x, w, acc2[0]);
            acc2[1] = fma2(h01.y, w, acc2[1]);
            acc2[2] = fma2(h23.x, w, acc2[2]);
            acc2[3] = fma2(h23.y, w, acc2[3]);
        }
        __syncthreads();
        if (kt + 2 < 8) {
            wtile_async(smem + P2_WB + (kt & 1) * 8192, W2 + (kt + 2) * 8192);
            CP_COMMIT();
        }
    }
    #pragma unroll
    for (int j = 0; j < 4; j++) {
        float c0, c1;
        upk2(acc2[j], c0, c1);
        *(float2*)(y2s + (rg4 * 4 + j) * M2M + cp2 * 2) = make_float2(c0, c1);
    }
    __syncthreads();

    // ---- LN2 + output ----
    for (int r = wid; r < 16; r += 8) {
        float s = 0.f, ss = 0.f;
        #pragma unroll
        for (int j = 0; j < 4; j++) {
            float v = y2s[r * M2M + lane + j * 32];
            s += v; ss += v * v;
        }
        #pragma unroll
        for (int off = 16; off; off >>= 1) {
            s  += __shfl_xor_sync(0xffffffffu, s, off);
            ss += __shfl_xor_sync(0xffffffffu, ss, off);
        }
        if (lane == 0) {
            float mu = s * (1.f / M2M);
            float var = ss * (1.f / M2M) - mu * mu;
            mu2[r] = mu;
            rs2[r] = rsqrtf(var + EPS_);
        }
    }
    __syncthreads();
    {
        const int m  = tid & 127;
        const int rb = (tid >> 7) * 8;
        float gv = g2[m], bv = b2[m];
        #pragma unroll
        for (int j = 0; j < 8; j++) {
            int r = rb + j;
            float v = (y2s[r * M2M + m] - mu2[r]) * rs2[r] * gv + bv;
            out[(size_t)(b0 + r) * M2M + m] = fmaxf(0.f, v);
        }
    }
}

// ---------------- launcher ----------------
extern "C" void kernel_launch(void* const* d_in, const int* in_sizes, int n_in,
                              void* d_out, int out_size) {
    const float* x     = (const float*)d_in[0];
    const void*  kpm   = d_in[2];
    const float* Wk    = (const float*)d_in[3];
    const float* query = (const float*)d_in[5];
    const float* W1    = (const float*)d_in[6];
    const float* g1    = (const float*)d_in[7];
    const float* b1    = (const float*)d_in[8];
    const float* W2    = (const float*)d_in[9];
    const float* g2    = (const float*)d_in[10];
    const float* b2    = (const float*)d_in[11];

    float* out_mlp  = (float*)d_out;                       // [B, 128]
    float* out_attn = (float*)d_out + (size_t)BB * M2M;    // [B, H, T]

    cudaFuncSetAttribute(k_attn, cudaFuncAttributeMaxDynamicSharedMemorySize,
                         SMEM1_F * 4);
    cudaFuncSetAttribute(k_mlp, cudaFuncAttributeMaxDynamicSharedMemorySize,
                         SMEM2_F * 4);

    // 3 noops FIRST: ncu empirically captures the 4th launch of the process,
    // which is now k_attn (finally profiling the dominant kernel).
    k_noop<<<1, 32>>>();
    k_noop<<<1, 32>>>();
    k_noop<<<1, 32>>>();
    k_attn<<<GRID_, 512, SMEM1_F * 4>>>(x, kpm, Wk, query, out_attn);
    k_mlp<<<BB / 16, 256, SMEM2_F * 4>>>(W1, g1, b1, W2, g2, b2, out_mlp);
}

// round 16
// speedup vs baseline: 1.0575x; 1.0134x over previous
#include <cuda_runtime.h>
#include <cstdint>

#define BB    2048
#define TT    64
#define CC    1024
#define HH    16
#define DKK   8
#define M1M   512
#define M2M   128
#define GRID_ 148
#define SCALE_ 0.35355339059327373f
#define EPS_   1e-5f
#define NEGINF_ (-3.402823466e38f)

// ---------------- device scratch (no allocations allowed) ----------------
__device__ float g_wq[HH * CC];          // folded query projection (scaled)
__device__ float g_pooled[BB * CC];      // attention-pooled features
__device__ int   g_mask_mode;            // 0=u8, 1=i32, 2=f32
__device__ unsigned int g_tk1;           // ticket counter (monotone)
__device__ volatile unsigned int g_rl1;  // release round (monotone)

// ---------------- f32x2 packed-math helpers ----------------
__device__ __forceinline__ void upk2(unsigned long long v, float& lo, float& hi) {
    asm("mov.b64 {%0,%1}, %2;" : "=f"(lo), "=f"(hi) : "l"(v));
}
__device__ __forceinline__ unsigned long long fma2(unsigned long long a,
                                                   unsigned long long b,
                                                   unsigned long long c) {
    unsigned long long d;
    asm("fma.rn.f32x2 %0, %1, %2, %3;" : "=l"(d) : "l"(a), "l"(b), "l"(c));
    return d;
}
__device__ __forceinline__ unsigned long long pk2s(float a) {
    unsigned long long r;
    asm("mov.b64 %0, {%1,%1};" : "=l"(r) : "f"(a));
    return r;
}

// ---------------- replay-safe device-wide barrier (all 148 CTAs resident) ----
__device__ __forceinline__ void gbar(unsigned int* tk, volatile unsigned int* rl) {
    __syncthreads();
    if (threadIdx.x == 0) {
        __threadfence();
        unsigned int t = atomicAdd(tk, 1u) + 1u;
        unsigned int round = (t + GRID_ - 1u) / GRID_;
        if (t == round * GRID_) {
            __threadfence();
            *rl = round;
        } else {
            while (*rl < round) { }
        }
        __threadfence();
    }
    __syncthreads();
}

// ---------------- k_attn smem layout (floats) ----------------
// wq[16384] | xs[2][16384] | att[1024] | p[256] | mrun[16] srun[16] fsc[16]
// msk[64] | att_p[512]
#define WQ_OFF   0
#define XS_OFF   16384
#define ATT_OFF  49152
#define P_OFF    50176
#define MR_OFF   50432
#define SR_OFF   50448
#define FS_OFF   50464
#define MSK_OFF  50480
#define ATP_OFF  50544
#define SMEM1_F  51056

__device__ __forceinline__ void tile_async256(float* dst, const float* src) {
    int tid = threadIdx.x;
    #pragma unroll
    for (int i = 0; i < 16; i++) {
        int e = (tid + i * 256) * 4;
        uint32_t sa = (uint32_t)__cvta_generic_to_shared(dst + e);
        asm volatile("cp.async.cg.shared.global [%0], [%1], 16;\n"
                     :: "r"(sa), "l"(src + e));
    }
}
#define CP_COMMIT() asm volatile("cp.async.commit_group;\n")
#define CP_WAIT1()  asm volatile("cp.async.wait_group 1;\n")
#define CP_WAIT0()  asm volatile("cp.async.wait_group 0;\n")

// ---------------- no-op kernel: occupies launches 1-3 so ncu's capture
// (the 4th launch of the process) lands on k_attn --------------------------
__global__ void k_noop() {}

// =====================================================================
// K1: 256 threads, 148 CTAs — wq fold + flash attention
// warp tile = 8 rows x 8 heads x 512 k (kh2 x rg2 x hg2); crossbar-minimal
// (256 KB/tile = fma floor). Regs ~218 — no spill at 256 threads.
// =====================================================================
__global__ void __launch_bounds__(256, 1)
k_attn(const float* __restrict__ x, const void* __restrict__ kpm,
       const float* __restrict__ Wk, const float* __restrict__ query,
       float* __restrict__ attn_out) {
    extern __shared__ float smem[];
    const int cta  = blockIdx.x;
    const int tid  = threadIdx.x;
    const int wid  = tid >> 5;
    const int lane = tid & 31;

    // ============ phase 0: CTAs 0..15 build g_wq; CTA0 mask fingerprint ======
    if (cta < 16) {
        float* wk_s = smem + XS_OFF;       // scratch
        float* q_s  = smem + ATT_OFF;
        const int c_base = cta * 64;
        const float4* src = (const float4*)(Wk + c_base * (HH * DKK));
        #pragma unroll
        for (int i = 0; i < 8; i++)
            ((float4*)wk_s)[tid + i * 256] = src[tid + i * 256];
        if (tid < 128) q_s[tid] = query[tid] * SCALE_;
        __syncthreads();
        const int h  = tid >> 4;
        const int cl = (tid & 15) * 4;
        #pragma unroll
        for (int j = 0; j < 4; j++) {
            float s = 0.f;
            #pragma unroll
            for (int d = 0; d < DKK; d++)
                s += q_s[h * DKK + d] * wk_s[(cl + j) * 128 + h * DKK + d];
            g_wq[h * CC + c_base + cl + j] = s;
        }
        if (cta == 0) {
            __shared__ int nonbin, oddpos;
            if (tid == 0) { nonbin = 0; oddpos = 0; }
            __syncthreads();
            const unsigned char* p = (const unsigned char*)kpm;
            int lnb = 0, lod = 0;
            int base = tid * 128;
            for (int i = 0; i < 128; i++) {
                unsigned char v = p[base + i];
                if (v > 1) lnb = 1;
                else if (v == 1 && ((base + i) & 3)) lod = 1;
            }
            if (lnb) atomicOr(&nonbin, 1);
            if (lod) atomicOr(&oddpos, 1);
            __syncthreads();
            if (tid == 0) g_mask_mode = nonbin ? 2 : (oddpos ? 0 : 1);
        }
        __syncthreads();
    }
    // everyone prefetches their first batch tile 0 before arriving
    tile_async256(smem + XS_OFF, x + (size_t)cta * (TT * CC));
    CP_COMMIT();
    gbar(&g_tk1, &g_rl1);

    // ============ phase 1 =================================================
    float* wq_s  = smem + WQ_OFF;
    float* xs    = smem + XS_OFF;
    float* att_s = smem + ATT_OFF;
    float* p_s   = smem + P_OFF;
    float* mrun  = smem + MR_OFF;
    float* srun  = smem + SR_OFF;
    float* fsc   = smem + FS_OFF;
    int*   msk_s = (int*)(smem + MSK_OFF);
    float* att_p = smem + ATP_OFF;     // [2 kh][16 h][16 t_local]

    // stage wq once (coalesced float4)
    #pragma unroll 4
    for (int i = tid; i < 4096; i += 256)
        ((float4*)wq_s)[i] = ((const float4*)g_wq)[i];

    const int mode = g_mask_mode;
    // 8 warps: kh(2) x hg(2) x rg(2); warp tile = 8 rows x 8 heads x 512 k
    const int khalf = wid >> 2;            // 0/1
    const int rgrp  = (wid & 1) * 8;       // tile-local rows
    const int hgrp  = ((wid >> 1) & 1) * 8;
    const int hc    = tid >> 4;            // pooling head (channels tid*4..+4)

    for (int b = cta; b < BB; b += GRID_) {
        const float* xb = x + (size_t)b * (TT * CC);
        __syncthreads();                     // protect smem state reuse
        if (tid < TT) {
            int mv;
            if (mode == 0)      mv = ((const unsigned char*)kpm)[b * TT + tid] != 0;
            else if (mode == 1) mv = ((const int*)kpm)[b * TT + tid] != 0;
            else                mv = ((const float*)kpm)[b * TT + tid] != 0.f;
            msk_s[tid] = mv;
        }
        if (tid < HH) { mrun[tid] = NEGINF_; srun[tid] = 0.f; }

        float4 pacc = make_float4(0.f, 0.f, 0.f, 0.f);

        for (int tile = 0; tile < 4; tile++) {
            int issued = 0;
            if (tile < 3) {
                tile_async256(xs + ((tile + 1) & 1) * 16384, xb + (tile + 1) * 16384);
                CP_COMMIT(); issued = 1;
            } else if (b + GRID_ < BB) {
                tile_async256(xs, x + (size_t)(b + GRID_) * (TT * CC));
                CP_COMMIT(); issued = 1;
            }
            if (issued) CP_WAIT1(); else CP_WAIT0();
            __syncthreads();

            float* xt = xs + (tile & 1) * 16384;
            // per-warp slices: 8 rows, 8 heads, 512 k (one half); ull = 2 floats
            const unsigned long long* xrp =
                (const unsigned long long*)(xt + rgrp * CC + khalf * 512);
            const unsigned long long* wqh =
                (const unsigned long long*)(wq_s + hgrp * CC + khalf * 512);

            unsigned long long acc[8][8];
            #pragma unroll
            for (int r = 0; r < 8; r++)
                #pragma unroll
                for (int h = 0; h < 8; h++) acc[r][h] = 0ull;

            #pragma unroll
            for (int it = 0; it < 8; it++) {
                const int ci = lane + it * 32;      // ull index within half
                unsigned long long xv[8];
                #pragma unroll
                for (int r = 0; r < 8; r++)
                    xv[r] = xrp[r * (CC / 2) + ci];
                #pragma unroll
                for (int h = 0; h < 8; h++) {
                    unsigned long long w = wqh[h * (CC / 2) + ci];
                    #pragma unroll
                    for (int r = 0; r < 8; r++)
                        acc[r][h] = fma2(xv[r], w, acc[r][h]);
                }
            }

            // staggered per-row reduction; write k-half partials
            #pragma unroll
            for (int r = 0; r < 8; r++) {
                float sv[8];
                #pragma unroll
                for (int h = 0; h < 8; h++) {
                    float lo, hi; upk2(acc[r][h], lo, hi);
                    sv[h] = lo + hi;
                }
                #pragma unroll
                for (int off = 16; off; off >>= 1)
                    #pragma unroll
                    for (int h = 0; h < 8; h++)
                        sv[h] += __shfl_xor_sync(0xffffffffu, sv[h], off);
                float v = sv[0];
                #pragma unroll
                for (int h = 1; h < 8; h++) v = (lane == h) ? sv[h] : v;
                if (lane < 8)
                    att_p[khalf * 256 + (hgrp + lane) * 16 + rgrp + r] = v;
            }
            __syncthreads();

            { // flash update: warp w handles heads 2w, 2w+1 (16 lanes each)
                const int h  = wid * 2 + (lane >> 4);
                const int tt = lane & 15;
                const int tg = tile * 16 + tt;
                float s_raw  = att_p[h * 16 + tt] + att_p[256 + h * 16 + tt];
                att_s[h * TT + tg] = s_raw;          // keep for finalize
                int   msk    = msk_s[tg];
                float sm     = msk ? NEGINF_ : s_raw;
                float tmax   = sm;
                #pragma unroll
                for (int off = 8; off; off >>= 1)
                    tmax = fmaxf(tmax, __shfl_xor_sync(0xffffffffu, tmax, off));
                float m_old = mrun[h];
                float m_new = fmaxf(m_old, tmax);
                float p     = msk ? 0.f : __expf(s_raw - m_new);
                float psum  = p;
                #pragma unroll
                for (int off = 8; off; off >>= 1)
                    psum += __shfl_xor_sync(0xffffffffu, psum, off);
                float f = __expf(m_old - m_new);
                p_s[h * 16 + tt] = p;
                if ((lane & 15) == 0) {
                    mrun[h] = m_new;
                    srun[h] = srun[h] * f + psum;
                    fsc[h]  = f;
                }
            }
            __syncthreads();

            { // pooled accumulation from resident smem tile: 4 ch/thread
                float f = fsc[hc];
                pacc.x *= f; pacc.y *= f; pacc.z *= f; pacc.w *= f;
                const float* xp = xt + tid * 4;
                const float* pp = p_s + hc * 16;
                #pragma unroll
                for (int t = 0; t < 16; t++) {
                    float p = pp[t];
                    float4 v = *(const float4*)(xp + t * CC);
                    pacc.x += p * v.x; pacc.y += p * v.y;
                    pacc.z += p * v.z; pacc.w += p * v.w;
                }
            }
            __syncthreads();
        }

        { // finalize: attn output + pooled
            const int h  = tid >> 4;
            const int t4 = (tid & 15) * 4;
            float m   = mrun[h];
            float inv = 1.f / srun[h];
            float4 o;
            float* op = &o.x;
            #pragma unroll
            for (int j = 0; j < 4; j++) {
                int t = t4 + j;
                op[j] = msk_s[t] ? 0.f : __expf(att_s[h * TT + t] - m) * inv;
            }
            *(float4*)(attn_out + (size_t)b * (HH * TT) + h * TT + t4) = o;

            float invp = 1.f / srun[hc];
            pacc.x *= invp; pacc.y *= invp; pacc.z *= invp; pacc.w *= invp;
            *(float4*)(g_pooled + (size_t)b * CC + tid * 4) = pacc;
        }
    }
}

// =====================================================================
// K2: MLP — proven cp.async + splat kernel (R11, 96 us). Unchanged.
// =====================================================================
#define P2_A     0
#define P2_WB    16384
#define P2_SP    32768
#define P2_YS    36864
#define P2_Y2    45056
#define P2_ST    47104
#define SMEM2_F  47168

__device__ __forceinline__ void wtile_async(float* dst, const float* src) {
    int tid = threadIdx.x;
    #pragma unroll
    for (int i = 0; i < 8; i++) {
        int e = (tid + i * 256) * 4;
        uint32_t sa = (uint32_t)__cvta_generic_to_shared(dst + e);
        asm volatile("cp.async.cg.shared.global [%0], [%1], 16;\n"
                     :: "r"(sa), "l"(src + e));
    }
}

__global__ void __launch_bounds__(256, 1)
k_mlp(const float* __restrict__ W1, const float* __restrict__ g1,
      const float* __restrict__ b1, const float* __restrict__ W2,
      const float* __restrict__ g2, const float* __restrict__ b2,
      float* __restrict__ out) {
    extern __shared__ float smem[];
    float* A   = smem + P2_A;
    float* ys  = smem + P2_YS;
    float* y2s = smem + P2_Y2;
    float* mu1 = smem + P2_ST;
    float* rs1 = mu1 + 16;
    float* mu2 = rs1 + 16;
    float* rs2 = mu2 + 16;

    const int cta  = blockIdx.x;
    const int tid  = threadIdx.x;
    const int wid  = tid >> 5;
    const int lane = tid & 31;
    const int b0   = cta * 16;

    for (int i = tid; i < 4096; i += 256)
        ((float4*)A)[i] = *(const float4*)(g_pooled + (size_t)b0 * CC + i * 4);

    wtile_async(smem + P2_WB, W1);
    CP_COMMIT();
    wtile_async(smem + P2_WB + 8192, W1 + 8192);
    CP_COMMIT();
    __syncthreads();

    // ---- GEMM1: 16x512x1024, thread = 4 cols x 8 rows ----
    const int cg  = tid & 127;
    const int rg2 = tid >> 7;
    unsigned long long acc[8][2];
    #pragma unroll
    for (int r = 0; r < 8; r++) { acc[r][0] = 0ull; acc[r][1] = 0ull; }

    const int kk_b = tid >> 4, r_b = tid & 15;
    for (int kt = 0; kt < 64; kt++) {
        float* wb = smem + P2_WB + (kt & 1) * 8192;
        float* sp = smem + P2_SP + (kt & 1) * 2048;
        if (kt < 63) CP_WAIT1(); else CP_WAIT0();
        {
            float a = A[r_b * CC + kt * 16 + kk_b];
            ((float2*)sp)[kk_b * 16 + r_b] = make_float2(a, a);
        }
        __syncthreads();
        #pragma unroll
        for (int kk = 0; kk < 16; kk++) {
            ulonglong2 w = *(const ulonglong2*)(wb + kk * 512 + cg * 4);
            const float* aspk = sp + (kk * 16 + rg2 * 8) * 2;
            #pragma unroll
            for (int j = 0; j < 4; j++) {
                ulonglong2 a2 = *(const ulonglong2*)(aspk + j * 4);
                acc[2*j  ][0] = fma2(a2.x, w.x, acc[2*j  ][0]);
                acc[2*j  ][1] = fma2(a2.x, w.y, acc[2*j  ][1]);
                acc[2*j+1][0] = fma2(a2.y, w.x, acc[2*j+1][0]);
                acc[2*j+1][1] = fma2(a2.y, w.y, acc[2*j+1][1]);
            }
        }
        __syncthreads();
        if (kt + 2 < 64) {
            wtile_async(smem + P2_WB + (kt & 1) * 8192, W1 + (kt + 2) * 8192);
            CP_COMMIT();
        }
    }
    #pragma unroll
    for (int r = 0; r < 8; r++) {
        float c0, c1, c2, c3;
        upk2(acc[r][0], c0, c1);
        upk2(acc[r][1], c2, c3);
        *(float4*)(ys + (rg2 * 8 + r) * M1M + cg * 4) = make_float4(c0, c1, c2, c3);
    }
    __syncthreads();

    // ---- LN1 ----
    for (int r = wid; r < 16; r += 8) {
        float s = 0.f, ss = 0.f;
        #pragma unroll
        for (int j = 0; j < 16; j++) {
            float v = ys[r * M1M + lane + j * 32];
            s += v; ss += v * v;
        }
        #pragma unroll
        for (int off = 16; off; off >>= 1) {
            s  += __shfl_xor_sync(0xffffffffu, s, off);
            ss += __shfl_xor_sync(0xffffffffu, ss, off);
        }
        if (lane == 0) {
            float mu = s * (1.f / M1M);
            float var = ss * (1.f / M1M) - mu * mu;
            mu1[r] = mu;
            rs1[r] = rsqrtf(var + EPS_);
        }
    }
    __syncthreads();
    {
        float2 gv = ((const float2*)g1)[tid];
        float2 bv = ((const float2*)b1)[tid];
        #pragma unroll
        for (int r = 0; r < 16; r++) {
            float m = mu1[r], rs = rs1[r];
            float2 v = *(float2*)(ys + r * M1M + 2 * tid);
            v.x = fmaxf(0.f, (v.x - m) * rs * gv.x + bv.x);
            v.y = fmaxf(0.f, (v.y - m) * rs * gv.y + bv.y);
            *(float2*)(ys + r * M1M + 2 * tid) = v;
        }
    }
    __syncthreads();

    // ---- GEMM2: 16x128x512 ----
    wtile_async(smem + P2_WB, W2);
    CP_COMMIT();
    wtile_async(smem + P2_WB + 8192, W2 + 8192);
    CP_COMMIT();

    const int cp2 = tid & 63;
    const int rg4 = tid >> 6;
    unsigned long long acc2[4] = {0ull, 0ull, 0ull, 0ull};

    for (int kt = 0; kt < 8; kt++) {
        float* wb = smem + P2_WB + (kt & 1) * 8192;
        float* sp = smem + P2_SP + (kt & 1) * 2048;
        if (kt < 7) CP_WAIT1(); else CP_WAIT0();
        for (int i = tid; i < 1024; i += 256) {
            int kk = i >> 4, r = i & 15;
            float v = ys[r * M1M + kt * 64 + kk];
            ((float2*)sp)[i] = make_float2(v, v);
        }
        __syncthreads();
        #pragma unroll
        for (int kk = 0; kk < 64; kk++) {
            unsigned long long w = *(const unsigned long long*)(wb + kk * 128 + cp2 * 2);
            const float* hk = sp + (kk * 16 + rg4 * 4) * 2;
            ulonglong2 h01 = *(const ulonglong2*)(hk);
            ulonglong2 h23 = *(const ulonglong2*)(hk + 4);
            acc2[0] = fma2(h01.x, w, acc2[0]);
            acc2[1] = fma2(h01.y, w, acc2[1]);
            acc2[2] = fma2(h23.x, w, acc2[2]);
            acc2[3] = fma2(h23.y, w, acc2[3]);
        }
        __syncthreads();
        if (kt + 2 < 8) {
            wtile_async(smem + P2_WB + (kt & 1) * 8192, W2 + (kt + 2) * 8192);
            CP_COMMIT();
        }
    }
    #pragma unroll
    for (int j = 0; j < 4; j++) {
        float c0, c1;
        upk2(acc2[j], c0, c1);
        *(float2*)(y2s + (rg4 * 4 + j) * M2M + cp2 * 2) = make_float2(c0, c1);
    }
    __syncthreads();

    // ---- LN2 + output ----
    for (int r = wid; r < 16; r += 8) {
        float s = 0.f, ss = 0.f;
        #pragma unroll
        for (int j = 0; j < 4; j++) {
            float v = y2s[r * M2M + lane + j * 32];
            s += v; ss += v * v;
        }
        #pragma unroll
        for (int off = 16; off; off >>= 1) {
            s  += __shfl_xor_sync(0xffffffffu, s, off);
            ss += __shfl_xor_sync(0xffffffffu, ss, off);
        }
        if (lane == 0) {
            float mu = s * (1.f / M2M);
            float var = ss * (1.f / M2M) - mu * mu;
            mu2[r] = mu;
            rs2[r] = rsqrtf(var + EPS_);
        }
    }
    __syncthreads();
    {
        const int m  = tid & 127;
        const int rb = (tid >> 7) * 8;
        float gv = g2[m], bv = b2[m];
        #pragma unroll
        for (int j = 0; j < 8; j++) {
            int r = rb + j;
            float v = (y2s[r * M2M + m] - mu2[r]) * rs2[r] * gv + bv;
            out[(size_t)(b0 + r) * M2M + m] = fmaxf(0.f, v);
        }
    }
}

// ---------------- launcher ----------------
extern "C" void kernel_launch(void* const* d_in, const int* in_sizes, int n_in,
                              void* d_out, int out_size) {
    const float* x     = (const float*)d_in[0];
    const void*  kpm   = d_in[2];
    const float* Wk    = (const float*)d_in[3];
    const float* query = (const float*)d_in[5];
    const float* W1    = (const float*)d_in[6];
    const float* g1    = (const float*)d_in[7];
    const float* b1    = (const float*)d_in[8];
    const float* W2    = (const float*)d_in[9];
    const float* g2    = (const float*)d_in[10];
    const float* b2    = (const float*)d_in[11];

    float* out_mlp  = (float*)d_out;                       // [B, 128]
    float* out_attn = (float*)d_out + (size_t)BB * M2M;    // [B, H, T]

    cudaFuncSetAttribute(k_attn, cudaFuncAttributeMaxDynamicSharedMemorySize,
                         SMEM1_F * 4);
    cudaFuncSetAttribute(k_mlp, cudaFuncAttributeMaxDynamicSharedMemorySize,
                         SMEM2_F * 4);

    // 3 noops FIRST: ncu captures the 4th launch of the process == k_attn.
    k_noop<<<1, 32>>>();
    k_noop<<<1, 32>>>();
    k_noop<<<1, 32>>>();
    k_attn<<<GRID_, 256, SMEM1_F * 4>>>(x, kpm, Wk, query, out_attn);
    k_mlp<<<BB / 16, 256, SMEM2_F * 4>>>(W1, g1, b1, W2, g2, b2, out_mlp);
}